// round 2
// baseline (speedup 1.0000x reference)
#include <cuda_runtime.h>
#include <cuda_bf16.h>
#include <cstdint>

// out[b, h] = verb_scores[b, idx[h]]
// BATCH = 131072, NUM_HOIS = 600, NUM_VERBS = 117.
// NOTE: reference uses jnp.int64 indices, but JAX without x64 silently emits
// int32 -> the device buffer is int32[600]. (R1 failed reading it as int64.)
// Pure HBM-bound: 314.6 MB stores + 61.3 MB reads -> ~49 us floor at 7.7 TB/s.

#define NUM_VERBS 117
#define NUM_HOIS  600
#define QUADS_PER_ROW (NUM_HOIS / 4)   // 150

__global__ __launch_bounds__(256) void scatter_verbs_kernel(
    const float* __restrict__ verb_scores,  // [BATCH, 117] fp32
    const int*   __restrict__ hoi_to_verb,  // [600] int32 (see note above)
    float*       __restrict__ out,          // [BATCH, 600] fp32
    int batch)
{
    int gid = blockIdx.x * blockDim.x + threadIdx.x;
    int total = batch * QUADS_PER_ROW;
    if (gid >= total) return;

    int b = gid / QUADS_PER_ROW;
    int q = gid - b * QUADS_PER_ROW;
    int h0 = q * 4;

    const float* row = verb_scores + (long long)b * NUM_VERBS;

    // Index table is 2.4 KB -> L1-resident for every SM.
    int i0 = __ldg(&hoi_to_verb[h0 + 0]);
    int i1 = __ldg(&hoi_to_verb[h0 + 1]);
    int i2 = __ldg(&hoi_to_verb[h0 + 2]);
    int i3 = __ldg(&hoi_to_verb[h0 + 3]);

    // 468 B/row: the 150 threads covering one row share ~4 cache lines -> L1 hits.
    float4 v;
    v.x = __ldg(&row[i0]);
    v.y = __ldg(&row[i1]);
    v.z = __ldg(&row[i2]);
    v.w = __ldg(&row[i3]);

    // Streaming store: output is write-once, keep it out of L2's working set.
    __stcs(reinterpret_cast<float4*>(out + (long long)b * NUM_HOIS + h0), v);
}

extern "C" void kernel_launch(void* const* d_in, const int* in_sizes, int n_in,
                              void* d_out, int out_size) {
    const float* verb_scores = (const float*)d_in[0];
    const int*   hoi_to_verb = (const int*)d_in[1];
    float* out = (float*)d_out;

    int batch = in_sizes[0] / NUM_VERBS;          // 131072
    int total = batch * QUADS_PER_ROW;            // 19,660,800 threads
    int threads = 256;
    int blocks = (total + threads - 1) / threads; // 76,800

    scatter_verbs_kernel<<<blocks, threads>>>(verb_scores, hoi_to_verb, out, batch);
}

// round 5
// speedup vs baseline: 1.2331x; 1.2331x over previous
#include <cuda_runtime.h>
#include <cuda_bf16.h>
#include <cstdint>

// out[b, h] = verb_scores[b, idx[h]]
// BATCH = 131072, NUM_HOIS = 600, NUM_VERBS = 117, idx is int32[600].
//
// R2 (flat, 96.5us) was L1tex-bound (89.5%) at DRAM 40%: per-quad strided
// index reloads cost ~64 L1 wavefronts per 512B of output. Fix: persistent
// threads — each thread owns one quad position q, loads its 4 indices ONCE
// (one int4), keeps them in registers, grid-strides over batch rows.
// 2x batch unroll for memory-level parallelism (8 gathers in flight).
// R3/R4 never ran (broker infra failures) — resubmitting.

#define NUM_VERBS 117
#define NUM_HOIS  600
#define QUADS_PER_ROW (NUM_HOIS / 4)   // 150

#define THREADS   256
#define BLOCKS    1200                  // 307200 threads = 2048 rows per wave

__global__ __launch_bounds__(THREADS) void scatter_verbs_kernel(
    const float* __restrict__ verb_scores,  // [BATCH, 117] fp32
    const int*   __restrict__ hoi_to_verb,  // [600] int32
    float*       __restrict__ out,          // [BATCH, 600] fp32
    int batch)
{
    const int g = blockIdx.x * THREADS + threadIdx.x;
    const int q  = g % QUADS_PER_ROW;       // fixed quad position for this thread
    const int b0 = g / QUADS_PER_ROW;       // starting batch row
    const int bstride = (BLOCKS * THREADS) / QUADS_PER_ROW;  // 2048

    // Load this thread's 4 indices ONCE (16B-aligned int4 at h0 = 4*q).
    const int4 idx = __ldg(reinterpret_cast<const int4*>(hoi_to_verb) + q);

    const long long h0 = (long long)q * 4;

    int b = b0;
    // Main loop: 2 rows per iteration -> 8 independent gathers in flight.
    for (; b + bstride < batch; b += 2 * bstride) {
        const float* rowA = verb_scores + (long long)b * NUM_VERBS;
        const float* rowB = verb_scores + (long long)(b + bstride) * NUM_VERBS;

        float4 va, vb;
        va.x = __ldg(&rowA[idx.x]);
        va.y = __ldg(&rowA[idx.y]);
        va.z = __ldg(&rowA[idx.z]);
        va.w = __ldg(&rowA[idx.w]);
        vb.x = __ldg(&rowB[idx.x]);
        vb.y = __ldg(&rowB[idx.y]);
        vb.z = __ldg(&rowB[idx.z]);
        vb.w = __ldg(&rowB[idx.w]);

        // Streaming stores: write-once 315 MB output, keep L2 for verb rows.
        __stcs(reinterpret_cast<float4*>(out + (long long)b * NUM_HOIS + h0), va);
        __stcs(reinterpret_cast<float4*>(out + (long long)(b + bstride) * NUM_HOIS + h0), vb);
    }
    // Tail (not taken for batch=131072; kept for generality).
    for (; b < batch; b += bstride) {
        const float* row = verb_scores + (long long)b * NUM_VERBS;
        float4 v;
        v.x = __ldg(&row[idx.x]);
        v.y = __ldg(&row[idx.y]);
        v.z = __ldg(&row[idx.z]);
        v.w = __ldg(&row[idx.w]);
        __stcs(reinterpret_cast<float4*>(out + (long long)b * NUM_HOIS + h0), v);
    }
}

extern "C" void kernel_launch(void* const* d_in, const int* in_sizes, int n_in,
                              void* d_out, int out_size) {
    const float* verb_scores = (const float*)d_in[0];
    const int*   hoi_to_verb = (const int*)d_in[1];
    float* out = (float*)d_out;

    int batch = in_sizes[0] / NUM_VERBS;    // 131072

    scatter_verbs_kernel<<<BLOCKS, THREADS>>>(verb_scores, hoi_to_verb, out, batch);
}

// round 8
// speedup vs baseline: 1.3442x; 1.0901x over previous
#include <cuda_runtime.h>
#include <cuda_bf16.h>
#include <cstdint>

// out[b, h] = verb_scores[b, idx[h]]
// BATCH = 131072, NUM_HOIS = 600, NUM_VERBS = 117, idx int32[600].
//
// R5 (72.9us): 1200 persistent blocks vs 888 resident (40 regs -> 6 blk/SM)
// => 1.48x wave-quantization penalty (49us ideal * 1.48 = 72.5us, matches).
// Fix: flat grid-stride mapping (coalesced int4 index reload, ~+20% L1 work)
// + __launch_bounds__(256,8) to cap regs at 32 -> 8 blk/SM -> grid 1184 =
// EXACTLY one resident wave at 100% occupancy.
// (R6/R7 submissions never ran — broker infra flake; R4==R5 source proved
// failures are content-independent. Resubmitting unchanged.)

#define NUM_VERBS 117u
#define NUM_HOIS  600u
#define QUADS_PER_ROW 150u

#define THREADS 256
#define BLOCKS  1184        // 148 SMs * 8 blocks/SM = one full resident wave

__global__ __launch_bounds__(THREADS, 8) void scatter_verbs_kernel(
    const float* __restrict__ verb_scores,  // [BATCH, 117] fp32
    const int*   __restrict__ hoi_to_verb,  // [600] int32
    float*       __restrict__ out,          // [BATCH, 600] fp32
    unsigned nquads)                        // batch * 150
{
    const unsigned stride = gridDim.x * THREADS;    // 303104 at BLOCKS=1184
    const int4* idx_tab = reinterpret_cast<const int4*>(hoi_to_verb);

    for (unsigned i = blockIdx.x * THREADS + threadIdx.x; i < nquads; i += stride) {
        unsigned b = i / QUADS_PER_ROW;             // mul-high, ~3 ALU ops
        unsigned q = i - b * QUADS_PER_ROW;

        // Lanes have consecutive q (mod row wrap) -> coalesced int4 load,
        // table is 2.4 KB and L1-resident: ~4 wavefronts/warp-iter.
        const int4 idx = __ldg(idx_tab + q);

        const float* row = verb_scores + b * NUM_VERBS;  // row is 468 B: L1 hits
        float4 v;
        v.x = __ldg(&row[idx.x]);
        v.y = __ldg(&row[idx.y]);
        v.z = __ldg(&row[idx.z]);
        v.w = __ldg(&row[idx.w]);

        // Streaming store: write-once 315 MB output, keep L2 for verb rows.
        __stcs(reinterpret_cast<float4*>(out + b * NUM_HOIS) + q, v);
    }
}

extern "C" void kernel_launch(void* const* d_in, const int* in_sizes, int n_in,
                              void* d_out, int out_size) {
    const float* verb_scores = (const float*)d_in[0];
    const int*   hoi_to_verb = (const int*)d_in[1];
    float* out = (float*)d_out;

    unsigned batch  = (unsigned)(in_sizes[0] / (int)NUM_VERBS);  // 131072
    unsigned nquads = batch * QUADS_PER_ROW;                     // 19,660,800

    scatter_verbs_kernel<<<BLOCKS, THREADS>>>(verb_scores, hoi_to_verb, out, nquads);
}